// round 13
// baseline (speedup 1.0000x reference)
#include <cuda_runtime.h>

// Problem constants
#define BP   128          // B*P
#define SEQ  1024         // S
#define DIM  1024         // D
#define NH   16           // heads
#define DH   64           // depth per head
#define SCALE 0.125f      // 1/sqrt(64)
#define SIGMA 0.1f

// ---------------- scratch (device globals; no allocation allowed) ------------
__device__ float g_qp[BP * DIM];
__device__ float g_kp[BP * DIM];
__device__ float g_vp[BP * DIM];
__device__ float g_part[32 * BP * DIM];    // per-s-chunk partial sums of attn·V
__device__ float g_zsum[32 * BP * NH];     // per-s-chunk exp sums
__device__ float g_zh[BP * DIM];           // merged attention output (mean_z)
__device__ float g_p3[12][BP * DIM];       // q/k/v GEMM k-split partials (4 each)
__device__ float g_pz[8][BP * DIM];        // z GEMM k-split partials

// ---------------- partial projection GEMM (k-ranged, 4x4 micro-tile) --------
// partial[m][n] = sum_{k in [kBase, kBase+kLen)} x[m][k] * W[k][n]
// Block: 128 rows x 32 cols, 256 threads, micro-tile 4x4.
__device__ __forceinline__ void proj_partial_body(const float* __restrict__ x,
                                                  const float* __restrict__ W,
                                                  float* __restrict__ partial,
                                                  int colBase, int kBase, int kLen)
{
    __shared__ float xs[32][132];   // [k][m], padded
    __shared__ float ws[32][36];    // [k][n], padded

    const int tid = threadIdx.x;          // 0..255
    const int tx  = tid & 7;              // 8 col-groups of 4
    const int ty  = tid >> 3;             // 32 row-groups of 4

    float acc[4][4];
#pragma unroll
    for (int i = 0; i < 4; i++)
#pragma unroll
        for (int j = 0; j < 4; j++) acc[i][j] = 0.f;

    for (int kk = kBase; kk < kBase + kLen; kk += 32) {
#pragma unroll
        for (int r = 0; r < 4; r++) {
            int i  = tid + r * 256;
            int m  = i >> 3;
            int kq = (i & 7) << 2;
            float4 v = *reinterpret_cast<const float4*>(x + m * DIM + kk + kq);
            xs[kq + 0][m] = v.x;
            xs[kq + 1][m] = v.y;
            xs[kq + 2][m] = v.z;
            xs[kq + 3][m] = v.w;
        }
        {
            int k  = tid >> 3;
            int nq = (tid & 7) << 2;
            *reinterpret_cast<float4*>(&ws[k][nq]) =
                *reinterpret_cast<const float4*>(W + (kk + k) * DIM + colBase + nq);
        }
        __syncthreads();

#pragma unroll 8
        for (int k = 0; k < 32; k++) {
            float4 a = *reinterpret_cast<const float4*>(&xs[k][ty << 2]);
            float4 b = *reinterpret_cast<const float4*>(&ws[k][tx << 2]);
            acc[0][0] += a.x * b.x; acc[0][1] += a.x * b.y;
            acc[0][2] += a.x * b.z; acc[0][3] += a.x * b.w;
            acc[1][0] += a.y * b.x; acc[1][1] += a.y * b.y;
            acc[1][2] += a.y * b.z; acc[1][3] += a.y * b.w;
            acc[2][0] += a.z * b.x; acc[2][1] += a.z * b.y;
            acc[2][2] += a.z * b.z; acc[2][3] += a.z * b.w;
            acc[3][0] += a.w * b.x; acc[3][1] += a.w * b.y;
            acc[3][2] += a.w * b.z; acc[3][3] += a.w * b.w;
        }
        __syncthreads();
    }

    int n0 = colBase + (tx << 2);
#pragma unroll
    for (int i = 0; i < 4; i++) {
        int m = (ty << 2) + i;
        float4 r;
        r.x = acc[i][0]; r.y = acc[i][1]; r.z = acc[i][2]; r.w = acc[i][3];
        *reinterpret_cast<float4*>(partial + m * DIM + n0) = r;
    }
}

// proj3: grid (32 col-tiles, 3 matrices, 4 k-quarters)
__global__ void __launch_bounds__(256)
proj3_kernel(const float* __restrict__ q, const float* __restrict__ k,
             const float* __restrict__ v,
             const float* __restrict__ Wq, const float* __restrict__ Wk,
             const float* __restrict__ Wv)
{
    const int mat = blockIdx.y;
    const int kq  = blockIdx.z;
    const float* x = (mat == 0) ? q  : (mat == 1) ? k  : v;
    const float* W = (mat == 0) ? Wq : (mat == 1) ? Wk : Wv;
    proj_partial_body(x, W, g_p3[mat * 4 + kq],
                      blockIdx.x * 32, kq * 256, 256);
}

// combine q/k/v partials + bias + sigma*noise -> g_qp/g_kp/g_vp
__global__ void __launch_bounds__(256)
combine3_kernel(const float* __restrict__ bq, const float* __restrict__ bk,
                const float* __restrict__ bv,
                const float* __restrict__ nq, const float* __restrict__ nk,
                const float* __restrict__ nv)
{
    const int mat = blockIdx.y;
    const float* b = (mat == 0) ? bq : (mat == 1) ? bk : bv;
    const float* n = (mat == 0) ? nq : (mat == 1) ? nk : nv;
    float* o       = (mat == 0) ? g_qp : (mat == 1) ? g_kp : g_vp;

    int i = (blockIdx.x * 256 + threadIdx.x) << 2;   // 128 blocks * 256 * 4 = 128K
    float4 p0 = *reinterpret_cast<const float4*>(&g_p3[mat * 4 + 0][i]);
    float4 p1 = *reinterpret_cast<const float4*>(&g_p3[mat * 4 + 1][i]);
    float4 p2 = *reinterpret_cast<const float4*>(&g_p3[mat * 4 + 2][i]);
    float4 p3 = *reinterpret_cast<const float4*>(&g_p3[mat * 4 + 3][i]);
    float4 bb = *reinterpret_cast<const float4*>(b + (i & (DIM - 1)));
    float4 nn = *reinterpret_cast<const float4*>(n + i);
    float4 r;
    r.x = ((p0.x + p1.x) + (p2.x + p3.x)) + bb.x + SIGMA * nn.x;
    r.y = ((p0.y + p1.y) + (p2.y + p3.y)) + bb.y + SIGMA * nn.y;
    r.z = ((p0.z + p1.z) + (p2.z + p3.z)) + bb.z + SIGMA * nn.z;
    r.w = ((p0.w + p1.w) + (p2.w + p3.w)) + bb.w + SIGMA * nn.w;
    *reinterpret_cast<float4*>(o + i) = r;
}

// projZ: grid (32 col-tiles, 1, 8 k-eighths)
__global__ void __launch_bounds__(256)
projZ_kernel(const float* __restrict__ Wz)
{
    const int kq = blockIdx.z;
    proj_partial_body(g_zh, Wz, g_pz[kq], blockIdx.x * 32, kq * 128, 128);
}

__global__ void __launch_bounds__(256)
combineZ_kernel(const float* __restrict__ bz, const float* __restrict__ nz,
                float* __restrict__ z_out)
{
    int i = (blockIdx.x * 256 + threadIdx.x) << 2;   // 128 blocks
    float4 s = make_float4(0.f, 0.f, 0.f, 0.f);
#pragma unroll
    for (int c = 0; c < 8; c++) {
        float4 p = *reinterpret_cast<const float4*>(&g_pz[c][i]);
        s.x += p.x; s.y += p.y; s.z += p.z; s.w += p.w;
    }
    float4 bb = *reinterpret_cast<const float4*>(bz + (i & (DIM - 1)));
    float4 nn = *reinterpret_cast<const float4*>(nz + i);
    float4 r;
    r.x = s.x + bb.x + SIGMA * nn.x;
    r.y = s.y + bb.y + SIGMA * nn.y;
    r.z = s.z + bb.z + SIGMA * nn.z;
    r.w = s.w + bb.w + SIGMA * nn.w;
    *reinterpret_cast<float4*>(z_out + i) = r;
}

// ---------------- copy K -> K_out (slot write) + logits + chunk exp-sums ----
// Streaming loop is R1/R5-verbatim; epilogue additionally produces per-chunk
// exp sums so the standalone softmax kernel can be dropped.
__global__ void __launch_bounds__(256)
copyK_kernel(const float* __restrict__ K, float* __restrict__ Kout,
             float* __restrict__ logits, const int* __restrict__ tptr)
{
    const int bp  = blockIdx.y;
    const int s0  = blockIdx.x * 32;
    const int tid = threadIdx.x;
    const int t   = *tptr;

    __shared__ float pds[32][256];   // per-s, per-thread partial dot
    __shared__ float we[32][NH + 1]; // exp(logit) per s-row, per head

    float4 q4 = *reinterpret_cast<const float4*>(g_qp + bp * DIM + (tid << 2));
    const float* kprow = g_kp + bp * DIM;
    const float* Kb = K    + (size_t)bp * SEQ * DIM;
    float*       Ob = Kout + (size_t)bp * SEQ * DIM;

#pragma unroll 4
    for (int sl = 0; sl < 32; sl++) {
        int s = s0 + sl;
        const float* src = (s == t) ? kprow : (Kb + (size_t)s * DIM);
        float4 v = *reinterpret_cast<const float4*>(src + (tid << 2));
        *reinterpret_cast<float4*>(Ob + (size_t)s * DIM + (tid << 2)) = v;
        pds[sl][tid] = v.x * q4.x + v.y * q4.y + v.z * q4.z + v.w * q4.w;
    }
    __syncthreads();

    for (int i = tid; i < 512; i += 256) {
        int h  = i & 15;
        int sl = i >> 4;
        float sum = 0.f;
#pragma unroll
        for (int j = 0; j < 16; j++) sum += pds[sl][(h << 4) + j];
        float l = sum * SCALE;
        logits[((size_t)(bp * NH + h)) * SEQ + s0 + sl] = l;
        we[sl][h] = __expf(l);
    }
    __syncthreads();

    if (tid < NH) {
        float z = 0.f;
#pragma unroll
        for (int sl = 0; sl < 32; sl++) z += we[sl][tid];
        g_zsum[((size_t)blockIdx.x * BP + bp) * NH + tid] = z;
    }
}

// ---------------- copy V -> V_out (slot write) + softmax + partials ---------
// Prologue normalizes this chunk's logits with the global exp-sum and writes
// the softmaxed attn output in place; streaming loop is R1/R5-verbatim.
__global__ void __launch_bounds__(256)
copyV_kernel(const float* __restrict__ V, float* __restrict__ Vout,
             float* __restrict__ attn, const int* __restrict__ tptr)
{
    const int bp  = blockIdx.y;
    const int s0  = blockIdx.x * 32;
    const int tid = threadIdx.x;
    const int t   = *tptr;

    __shared__ float zinv[NH];
    __shared__ float wa[32][NH + 1];

    if (tid < NH) {
        float z = 0.f;
#pragma unroll
        for (int c = 0; c < 32; c++) z += g_zsum[((size_t)c * BP + bp) * NH + tid];
        zinv[tid] = 1.f / z;
    }
    __syncthreads();

#pragma unroll
    for (int r = 0; r < 2; r++) {
        int i  = tid + r * 256;            // 0..511
        int sl = i >> 4;
        int h  = i & 15;
        size_t idx = ((size_t)(bp * NH + h)) * SEQ + s0 + sl;
        float w = __expf(attn[idx]) * zinv[h];
        wa[sl][h] = w;
        attn[idx] = w;
    }
    __syncthreads();

    const float* vprow = g_vp + bp * DIM;
    const float* Vb = V    + (size_t)bp * SEQ * DIM;
    float*       Ob = Vout + (size_t)bp * SEQ * DIM;

    const int h = tid >> 4;   // head of cols 4t..4t+3
    float4 acc = make_float4(0.f, 0.f, 0.f, 0.f);

#pragma unroll 4
    for (int sl = 0; sl < 32; sl++) {
        int s = s0 + sl;
        const float* src = (s == t) ? vprow : (Vb + (size_t)s * DIM);
        float4 v = *reinterpret_cast<const float4*>(src + (tid << 2));
        *reinterpret_cast<float4*>(Ob + (size_t)s * DIM + (tid << 2)) = v;
        float a = wa[sl][h];
        acc.x += a * v.x; acc.y += a * v.y; acc.z += a * v.z; acc.w += a * v.w;
    }
    *reinterpret_cast<float4*>(g_part + ((size_t)blockIdx.x * BP + bp) * DIM + (tid << 2)) = acc;
}

// ---------------- reduce the 32 s-chunk partials into g_zh (float4) ---------
__global__ void __launch_bounds__(256)
reduce_kernel()
{
    int i = (blockIdx.x * 256 + threadIdx.x) << 2;   // 128 blocks over BP*DIM
    float4 s = make_float4(0.f, 0.f, 0.f, 0.f);
#pragma unroll
    for (int c = 0; c < 32; c++) {
        float4 p = *reinterpret_cast<const float4*>(&g_part[(size_t)c * (BP * DIM) + i]);
        s.x += p.x; s.y += p.y; s.z += p.z; s.w += p.w;
    }
    *reinterpret_cast<float4*>(&g_zh[i]) = s;
}

// ---------------- launch ----------------------------------------------------
extern "C" void kernel_launch(void* const* d_in, const int* in_sizes, int n_in,
                              void* d_out, int out_size)
{
    const float* q   = (const float*)d_in[0];
    const float* k   = (const float*)d_in[1];
    const float* v   = (const float*)d_in[2];
    const float* Kin = (const float*)d_in[3];
    const float* Vin = (const float*)d_in[4];
    const float* Wq  = (const float*)d_in[5];
    const float* bq  = (const float*)d_in[6];
    const float* Wk  = (const float*)d_in[7];
    const float* bk  = (const float*)d_in[8];
    const float* Wv  = (const float*)d_in[9];
    const float* bv  = (const float*)d_in[10];
    const float* Wz  = (const float*)d_in[11];
    const float* bz  = (const float*)d_in[12];
    const float* nq  = (const float*)d_in[13];
    const float* nk  = (const float*)d_in[14];
    const float* nv  = (const float*)d_in[15];
    const float* nz  = (const float*)d_in[16];
    const int* tstep = (const int*)d_in[17];

    float* out   = (float*)d_out;
    float* z_out = out;                                       // 128*1024
    float* K_out = out + (size_t)BP * DIM;                    // 128*1024*1024
    float* V_out = K_out + (size_t)BP * SEQ * DIM;
    float* attn  = V_out + (size_t)BP * SEQ * DIM;            // 128*16*1024

    // 1. q/k/v projection partials (k-split x4, 4x4 micro-tile) + combine
    proj3_kernel<<<dim3(32, 3, 4), 256>>>(q, k, v, Wq, Wk, Wv);
    combine3_kernel<<<dim3(128, 3), 256>>>(bq, bk, bv, nq, nk, nv);
    // 2. K copy (slot write at t) + logits + per-chunk exp sums
    copyK_kernel<<<dim3(32, BP), 256>>>(Kin, K_out, attn, tstep);
    // 3. V copy (slot write at t) + softmaxed attn in place + partials
    copyV_kernel<<<dim3(32, BP), 256>>>(Vin, V_out, attn, tstep);
    // 4. reduce partials -> zh
    reduce_kernel<<<128, 256>>>();
    // 5. z projection partials (k-split x8) + combine
    projZ_kernel<<<dim3(32, 1, 8), 256>>>(Wz);
    combineZ_kernel<<<128, 256>>>(bz, nz, z_out);
}

// round 14
// speedup vs baseline: 1.4494x; 1.4494x over previous
#include <cuda_runtime.h>

// Problem constants
#define BP   128          // B*P
#define SEQ  1024         // S
#define DIM  1024         // D
#define NH   16           // heads
#define DH   64           // depth per head
#define SCALE 0.125f      // 1/sqrt(64)
#define SIGMA 0.1f

// ---------------- scratch (device globals; no allocation allowed) ------------
__device__ float g_qp[BP * DIM];
__device__ float g_kp[BP * DIM];
__device__ float g_vp[BP * DIM];
__device__ float g_part[32 * BP * DIM];    // per-s-chunk partial sums of attn·V
__device__ float g_zsum[32 * BP * NH];     // per-s-chunk exp sums
__device__ float g_zh[BP * DIM];           // merged attention output (mean_z)
__device__ float g_p3[12][BP * DIM];       // q/k/v GEMM k-split partials (4 each)
__device__ float g_pz[8][BP * DIM];        // z GEMM k-split partials

// ---------------- partial projection GEMM (k-ranged, 4x4 micro-tile) --------
__device__ __forceinline__ void proj_partial_body(const float* __restrict__ x,
                                                  const float* __restrict__ W,
                                                  float* __restrict__ partial,
                                                  int colBase, int kBase, int kLen)
{
    __shared__ float xs[32][132];   // [k][m], padded
    __shared__ float ws[32][36];    // [k][n], padded

    const int tid = threadIdx.x;          // 0..255
    const int tx  = tid & 7;              // 8 col-groups of 4
    const int ty  = tid >> 3;             // 32 row-groups of 4

    float acc[4][4];
#pragma unroll
    for (int i = 0; i < 4; i++)
#pragma unroll
        for (int j = 0; j < 4; j++) acc[i][j] = 0.f;

    for (int kk = kBase; kk < kBase + kLen; kk += 32) {
#pragma unroll
        for (int r = 0; r < 4; r++) {
            int i  = tid + r * 256;
            int m  = i >> 3;
            int kq = (i & 7) << 2;
            float4 v = *reinterpret_cast<const float4*>(x + m * DIM + kk + kq);
            xs[kq + 0][m] = v.x;
            xs[kq + 1][m] = v.y;
            xs[kq + 2][m] = v.z;
            xs[kq + 3][m] = v.w;
        }
        {
            int k  = tid >> 3;
            int nq = (tid & 7) << 2;
            *reinterpret_cast<float4*>(&ws[k][nq]) =
                *reinterpret_cast<const float4*>(W + (kk + k) * DIM + colBase + nq);
        }
        __syncthreads();

#pragma unroll 8
        for (int k = 0; k < 32; k++) {
            float4 a = *reinterpret_cast<const float4*>(&xs[k][ty << 2]);
            float4 b = *reinterpret_cast<const float4*>(&ws[k][tx << 2]);
            acc[0][0] += a.x * b.x; acc[0][1] += a.x * b.y;
            acc[0][2] += a.x * b.z; acc[0][3] += a.x * b.w;
            acc[1][0] += a.y * b.x; acc[1][1] += a.y * b.y;
            acc[1][2] += a.y * b.z; acc[1][3] += a.y * b.w;
            acc[2][0] += a.z * b.x; acc[2][1] += a.z * b.y;
            acc[2][2] += a.z * b.z; acc[2][3] += a.z * b.w;
            acc[3][0] += a.w * b.x; acc[3][1] += a.w * b.y;
            acc[3][2] += a.w * b.z; acc[3][3] += a.w * b.w;
        }
        __syncthreads();
    }

    int n0 = colBase + (tx << 2);
#pragma unroll
    for (int i = 0; i < 4; i++) {
        int m = (ty << 2) + i;
        float4 r;
        r.x = acc[i][0]; r.y = acc[i][1]; r.z = acc[i][2]; r.w = acc[i][3];
        *reinterpret_cast<float4*>(partial + m * DIM + n0) = r;
    }
}

// proj3: grid (32 col-tiles, 3 matrices, 4 k-quarters)
__global__ void __launch_bounds__(256)
proj3_kernel(const float* __restrict__ q, const float* __restrict__ k,
             const float* __restrict__ v,
             const float* __restrict__ Wq, const float* __restrict__ Wk,
             const float* __restrict__ Wv)
{
    const int mat = blockIdx.y;
    const int kq  = blockIdx.z;
    const float* x = (mat == 0) ? q  : (mat == 1) ? k  : v;
    const float* W = (mat == 0) ? Wq : (mat == 1) ? Wk : Wv;
    proj_partial_body(x, W, g_p3[mat * 4 + kq],
                      blockIdx.x * 32, kq * 256, 256);
}

// combine q/k/v partials + bias + sigma*noise -> g_qp/g_kp/g_vp
__global__ void __launch_bounds__(256)
combine3_kernel(const float* __restrict__ bq, const float* __restrict__ bk,
                const float* __restrict__ bv,
                const float* __restrict__ nq, const float* __restrict__ nk,
                const float* __restrict__ nv)
{
    const int mat = blockIdx.y;
    const float* b = (mat == 0) ? bq : (mat == 1) ? bk : bv;
    const float* n = (mat == 0) ? nq : (mat == 1) ? nk : nv;
    float* o       = (mat == 0) ? g_qp : (mat == 1) ? g_kp : g_vp;

    int i = (blockIdx.x * 256 + threadIdx.x) << 2;   // 128 blocks * 256 * 4 = 128K
    float4 p0 = *reinterpret_cast<const float4*>(&g_p3[mat * 4 + 0][i]);
    float4 p1 = *reinterpret_cast<const float4*>(&g_p3[mat * 4 + 1][i]);
    float4 p2 = *reinterpret_cast<const float4*>(&g_p3[mat * 4 + 2][i]);
    float4 p3 = *reinterpret_cast<const float4*>(&g_p3[mat * 4 + 3][i]);
    float4 bb = *reinterpret_cast<const float4*>(b + (i & (DIM - 1)));
    float4 nn = *reinterpret_cast<const float4*>(n + i);
    float4 r;
    r.x = ((p0.x + p1.x) + (p2.x + p3.x)) + bb.x + SIGMA * nn.x;
    r.y = ((p0.y + p1.y) + (p2.y + p3.y)) + bb.y + SIGMA * nn.y;
    r.z = ((p0.z + p1.z) + (p2.z + p3.z)) + bb.z + SIGMA * nn.z;
    r.w = ((p0.w + p1.w) + (p2.w + p3.w)) + bb.w + SIGMA * nn.w;
    *reinterpret_cast<float4*>(o + i) = r;
}

// projZ: grid (32 col-tiles, 1, 8 k-eighths)
__global__ void __launch_bounds__(256)
projZ_kernel(const float* __restrict__ Wz)
{
    const int kq = blockIdx.z;
    proj_partial_body(g_zh, Wz, g_pz[kq], blockIdx.x * 32, kq * 128, 128);
}

__global__ void __launch_bounds__(256)
combineZ_kernel(const float* __restrict__ bz, const float* __restrict__ nz,
                float* __restrict__ z_out)
{
    int i = (blockIdx.x * 256 + threadIdx.x) << 2;   // 128 blocks
    float4 s = make_float4(0.f, 0.f, 0.f, 0.f);
#pragma unroll
    for (int c = 0; c < 8; c++) {
        float4 p = *reinterpret_cast<const float4*>(&g_pz[c][i]);
        s.x += p.x; s.y += p.y; s.z += p.z; s.w += p.w;
    }
    float4 bb = *reinterpret_cast<const float4*>(bz + (i & (DIM - 1)));
    float4 nn = *reinterpret_cast<const float4*>(nz + i);
    float4 r;
    r.x = s.x + bb.x + SIGMA * nn.x;
    r.y = s.y + bb.y + SIGMA * nn.y;
    r.z = s.z + bb.z + SIGMA * nn.z;
    r.w = s.w + bb.w + SIGMA * nn.w;
    *reinterpret_cast<float4*>(z_out + i) = r;
}

// ---------------- copy K -> K_out (slot write) + logits + chunk exp-sums ----
// Streaming loop R1/R5-verbatim; extra work is strictly in the epilogue.
__global__ void __launch_bounds__(256)
copyK_kernel(const float* __restrict__ K, float* __restrict__ Kout,
             float* __restrict__ logits, const int* __restrict__ tptr)
{
    const int bp  = blockIdx.y;
    const int s0  = blockIdx.x * 32;
    const int tid = threadIdx.x;
    const int t   = *tptr;

    __shared__ float pds[32][256];   // per-s, per-thread partial dot
    __shared__ float we[32][NH + 1]; // exp(logit) per s-row, per head

    float4 q4 = *reinterpret_cast<const float4*>(g_qp + bp * DIM + (tid << 2));
    const float* kprow = g_kp + bp * DIM;
    const float* Kb = K    + (size_t)bp * SEQ * DIM;
    float*       Ob = Kout + (size_t)bp * SEQ * DIM;

#pragma unroll 4
    for (int sl = 0; sl < 32; sl++) {
        int s = s0 + sl;
        const float* src = (s == t) ? kprow : (Kb + (size_t)s * DIM);
        float4 v = *reinterpret_cast<const float4*>(src + (tid << 2));
        *reinterpret_cast<float4*>(Ob + (size_t)s * DIM + (tid << 2)) = v;
        pds[sl][tid] = v.x * q4.x + v.y * q4.y + v.z * q4.z + v.w * q4.w;
    }
    __syncthreads();

    for (int i = tid; i < 512; i += 256) {
        int h  = i & 15;
        int sl = i >> 4;
        float sum = 0.f;
#pragma unroll
        for (int j = 0; j < 16; j++) sum += pds[sl][(h << 4) + j];
        float l = sum * SCALE;
        logits[((size_t)(bp * NH + h)) * SEQ + s0 + sl] = l;
        we[sl][h] = __expf(l);
    }
    __syncthreads();

    if (tid < NH) {
        float z = 0.f;
#pragma unroll
        for (int sl = 0; sl < 32; sl++) z += we[sl][tid];
        g_zsum[((size_t)blockIdx.x * BP + bp) * NH + tid] = z;
    }
}

// ---------------- normalize: attn = exp(logit) * zinv (coalesced, no reductions)
// one block per bp: 16 threads fold the 32 chunk exp-sums, then 256 threads
// stream the bp's 16 rows (16K floats) as float4.
__global__ void __launch_bounds__(256)
normalize_kernel(float* __restrict__ attn)
{
    const int bp  = blockIdx.x;
    const int tid = threadIdx.x;

    __shared__ float zinv[NH];
    if (tid < NH) {
        float z = 0.f;
#pragma unroll
        for (int c = 0; c < 32; c++) z += g_zsum[((size_t)c * BP + bp) * NH + tid];
        zinv[tid] = 1.f / z;
    }
    __syncthreads();

    float* base = attn + (size_t)bp * NH * SEQ;
#pragma unroll
    for (int r = 0; r < 16; r++) {
        int i = (r * 256 + tid) << 2;            // 0..16K floats
        float s = zinv[i >> 10];                  // row = i / SEQ
        float4 l = *reinterpret_cast<const float4*>(base + i);
        float4 w;
        w.x = __expf(l.x) * s;
        w.y = __expf(l.y) * s;
        w.z = __expf(l.z) * s;
        w.w = __expf(l.w) * s;
        *reinterpret_cast<float4*>(base + i) = w;
    }
}

// ---------------- copy V -> V_out (slot write) + attn-weighted partials -----
// (R1/R5/R12 form — verbatim; reads pre-normalized attn)
__global__ void __launch_bounds__(256)
copyV_kernel(const float* __restrict__ V, float* __restrict__ Vout,
             const float* __restrict__ attn, const int* __restrict__ tptr)
{
    const int bp  = blockIdx.y;
    const int s0  = blockIdx.x * 32;
    const int tid = threadIdx.x;
    const int t   = *tptr;

    __shared__ float as[NH][32];
    for (int i = tid; i < NH * 32; i += 256) {
        int h  = i >> 5;
        int sl = i & 31;
        as[h][sl] = attn[((size_t)(bp * NH + h)) * SEQ + s0 + sl];
    }
    __syncthreads();

    const float* vprow = g_vp + bp * DIM;
    const float* Vb = V    + (size_t)bp * SEQ * DIM;
    float*       Ob = Vout + (size_t)bp * SEQ * DIM;

    const int h = tid >> 4;   // head of cols 4t..4t+3
    float4 acc = make_float4(0.f, 0.f, 0.f, 0.f);

#pragma unroll 4
    for (int sl = 0; sl < 32; sl++) {
        int s = s0 + sl;
        const float* src = (s == t) ? vprow : (Vb + (size_t)s * DIM);
        float4 v = *reinterpret_cast<const float4*>(src + (tid << 2));
        *reinterpret_cast<float4*>(Ob + (size_t)s * DIM + (tid << 2)) = v;
        float a = as[h][sl];
        acc.x += a * v.x; acc.y += a * v.y; acc.z += a * v.z; acc.w += a * v.w;
    }
    *reinterpret_cast<float4*>(g_part + ((size_t)blockIdx.x * BP + bp) * DIM + (tid << 2)) = acc;
}

// ---------------- reduce the 32 s-chunk partials into g_zh (float4) ---------
__global__ void __launch_bounds__(256)
reduce_kernel()
{
    int i = (blockIdx.x * 256 + threadIdx.x) << 2;   // 128 blocks over BP*DIM
    float4 s = make_float4(0.f, 0.f, 0.f, 0.f);
#pragma unroll
    for (int c = 0; c < 32; c++) {
        float4 p = *reinterpret_cast<const float4*>(&g_part[(size_t)c * (BP * DIM) + i]);
        s.x += p.x; s.y += p.y; s.z += p.z; s.w += p.w;
    }
    *reinterpret_cast<float4*>(&g_zh[i]) = s;
}

// ---------------- launch ----------------------------------------------------
extern "C" void kernel_launch(void* const* d_in, const int* in_sizes, int n_in,
                              void* d_out, int out_size)
{
    const float* q   = (const float*)d_in[0];
    const float* k   = (const float*)d_in[1];
    const float* v   = (const float*)d_in[2];
    const float* Kin = (const float*)d_in[3];
    const float* Vin = (const float*)d_in[4];
    const float* Wq  = (const float*)d_in[5];
    const float* bq  = (const float*)d_in[6];
    const float* Wk  = (const float*)d_in[7];
    const float* bk  = (const float*)d_in[8];
    const float* Wv  = (const float*)d_in[9];
    const float* bv  = (const float*)d_in[10];
    const float* Wz  = (const float*)d_in[11];
    const float* bz  = (const float*)d_in[12];
    const float* nq  = (const float*)d_in[13];
    const float* nk  = (const float*)d_in[14];
    const float* nv  = (const float*)d_in[15];
    const float* nz  = (const float*)d_in[16];
    const int* tstep = (const int*)d_in[17];

    float* out   = (float*)d_out;
    float* z_out = out;                                       // 128*1024
    float* K_out = out + (size_t)BP * DIM;                    // 128*1024*1024
    float* V_out = K_out + (size_t)BP * SEQ * DIM;
    float* attn  = V_out + (size_t)BP * SEQ * DIM;            // 128*16*1024

    // 1. q/k/v projection partials (k-split x4, 4x4 micro-tile) + combine
    proj3_kernel<<<dim3(32, 3, 4), 256>>>(q, k, v, Wq, Wk, Wv);
    combine3_kernel<<<dim3(128, 3), 256>>>(bq, bk, bv, nq, nk, nv);
    // 2. K copy (slot write at t) + logits + per-chunk exp sums
    copyK_kernel<<<dim3(32, BP), 256>>>(Kin, K_out, attn, tstep);
    // 3. normalize logits -> softmaxed attn (elementwise, no row reductions)
    normalize_kernel<<<BP, 256>>>(attn);
    // 4. V copy (slot write at t) fused with attn-weighted partial sums
    copyV_kernel<<<dim3(32, BP), 256>>>(Vin, V_out, attn, tstep);
    // 5. reduce partials -> zh
    reduce_kernel<<<128, 256>>>();
    // 6. z projection partials (k-split x8) + combine
    projZ_kernel<<<dim3(32, 1, 8), 256>>>(Wz);
    combineZ_kernel<<<128, 256>>>(bz, nz, z_out);
}

// round 15
// speedup vs baseline: 1.4960x; 1.0321x over previous
#include <cuda_runtime.h>

// Problem constants
#define BP   128          // B*P
#define SEQ  1024         // S
#define DIM  1024         // D
#define NH   16           // heads
#define DH   64           // depth per head
#define SCALE 0.125f      // 1/sqrt(64)
#define SIGMA 0.1f

// ---------------- scratch (device globals; no allocation allowed) ------------
__device__ float g_qp[BP * DIM];
__device__ float g_kp[BP * DIM];
__device__ float g_vp[BP * DIM];
__device__ float g_part[32 * BP * DIM];    // per-s-chunk partial sums of attn·V
__device__ float g_zh[BP * DIM];           // merged attention output (mean_z)
__device__ float g_p3[12][BP * DIM];       // q/k/v GEMM k-split partials (4 each)
__device__ float g_pz[8][BP * DIM];        // z GEMM k-split partials

// ---------------- partial projection GEMM (k-ranged, 4x4 micro-tile) --------
// partial[m][n] = sum_{k in [kBase, kBase+kLen)} x[m][k] * W[k][n]
// Block: 128 rows x 32 cols, 256 threads, micro-tile 4x4.
__device__ __forceinline__ void proj_partial_body(const float* __restrict__ x,
                                                  const float* __restrict__ W,
                                                  float* __restrict__ partial,
                                                  int colBase, int kBase, int kLen)
{
    __shared__ float xs[32][132];   // [k][m], padded
    __shared__ float ws[32][36];    // [k][n], padded

    const int tid = threadIdx.x;          // 0..255
    const int tx  = tid & 7;              // 8 col-groups of 4
    const int ty  = tid >> 3;             // 32 row-groups of 4

    float acc[4][4];
#pragma unroll
    for (int i = 0; i < 4; i++)
#pragma unroll
        for (int j = 0; j < 4; j++) acc[i][j] = 0.f;

    for (int kk = kBase; kk < kBase + kLen; kk += 32) {
#pragma unroll
        for (int r = 0; r < 4; r++) {
            int i  = tid + r * 256;
            int m  = i >> 3;
            int kq = (i & 7) << 2;
            float4 v = *reinterpret_cast<const float4*>(x + m * DIM + kk + kq);
            xs[kq + 0][m] = v.x;
            xs[kq + 1][m] = v.y;
            xs[kq + 2][m] = v.z;
            xs[kq + 3][m] = v.w;
        }
        {
            int k  = tid >> 3;
            int nq = (tid & 7) << 2;
            *reinterpret_cast<float4*>(&ws[k][nq]) =
                *reinterpret_cast<const float4*>(W + (kk + k) * DIM + colBase + nq);
        }
        __syncthreads();

#pragma unroll 8
        for (int k = 0; k < 32; k++) {
            float4 a = *reinterpret_cast<const float4*>(&xs[k][ty << 2]);
            float4 b = *reinterpret_cast<const float4*>(&ws[k][tx << 2]);
            acc[0][0] += a.x * b.x; acc[0][1] += a.x * b.y;
            acc[0][2] += a.x * b.z; acc[0][3] += a.x * b.w;
            acc[1][0] += a.y * b.x; acc[1][1] += a.y * b.y;
            acc[1][2] += a.y * b.z; acc[1][3] += a.y * b.w;
            acc[2][0] += a.z * b.x; acc[2][1] += a.z * b.y;
            acc[2][2] += a.z * b.z; acc[2][3] += a.z * b.w;
            acc[3][0] += a.w * b.x; acc[3][1] += a.w * b.y;
            acc[3][2] += a.w * b.z; acc[3][3] += a.w * b.w;
        }
        __syncthreads();
    }

    int n0 = colBase + (tx << 2);
#pragma unroll
    for (int i = 0; i < 4; i++) {
        int m = (ty << 2) + i;
        float4 r;
        r.x = acc[i][0]; r.y = acc[i][1]; r.z = acc[i][2]; r.w = acc[i][3];
        *reinterpret_cast<float4*>(partial + m * DIM + n0) = r;
    }
}

// proj3: grid (32 col-tiles, 3 matrices, 4 k-quarters)
__global__ void __launch_bounds__(256)
proj3_kernel(const float* __restrict__ q, const float* __restrict__ k,
             const float* __restrict__ v,
             const float* __restrict__ Wq, const float* __restrict__ Wk,
             const float* __restrict__ Wv)
{
    const int mat = blockIdx.y;
    const int kq  = blockIdx.z;
    const float* x = (mat == 0) ? q  : (mat == 1) ? k  : v;
    const float* W = (mat == 0) ? Wq : (mat == 1) ? Wk : Wv;
    proj_partial_body(x, W, g_p3[mat * 4 + kq],
                      blockIdx.x * 32, kq * 256, 256);
}

// combine q/k/v partials + bias + sigma*noise -> g_qp/g_kp/g_vp
__global__ void __launch_bounds__(256)
combine3_kernel(const float* __restrict__ bq, const float* __restrict__ bk,
                const float* __restrict__ bv,
                const float* __restrict__ nq, const float* __restrict__ nk,
                const float* __restrict__ nv)
{
    const int mat = blockIdx.y;
    const float* b = (mat == 0) ? bq : (mat == 1) ? bk : bv;
    const float* n = (mat == 0) ? nq : (mat == 1) ? nk : nv;
    float* o       = (mat == 0) ? g_qp : (mat == 1) ? g_kp : g_vp;

    int i = (blockIdx.x * 256 + threadIdx.x) << 2;   // 128 blocks * 256 * 4 = 128K
    float4 p0 = *reinterpret_cast<const float4*>(&g_p3[mat * 4 + 0][i]);
    float4 p1 = *reinterpret_cast<const float4*>(&g_p3[mat * 4 + 1][i]);
    float4 p2 = *reinterpret_cast<const float4*>(&g_p3[mat * 4 + 2][i]);
    float4 p3 = *reinterpret_cast<const float4*>(&g_p3[mat * 4 + 3][i]);
    float4 bb = *reinterpret_cast<const float4*>(b + (i & (DIM - 1)));
    float4 nn = *reinterpret_cast<const float4*>(n + i);
    float4 r;
    r.x = ((p0.x + p1.x) + (p2.x + p3.x)) + bb.x + SIGMA * nn.x;
    r.y = ((p0.y + p1.y) + (p2.y + p3.y)) + bb.y + SIGMA * nn.y;
    r.z = ((p0.z + p1.z) + (p2.z + p3.z)) + bb.z + SIGMA * nn.z;
    r.w = ((p0.w + p1.w) + (p2.w + p3.w)) + bb.w + SIGMA * nn.w;
    *reinterpret_cast<float4*>(o + i) = r;
}

// projZ: grid (32 col-tiles, 1, 8 k-eighths)
__global__ void __launch_bounds__(256)
projZ_kernel(const float* __restrict__ Wz)
{
    const int kq = blockIdx.z;
    proj_partial_body(g_zh, Wz, g_pz[kq], blockIdx.x * 32, kq * 128, 128);
}

__global__ void __launch_bounds__(256)
combineZ_kernel(const float* __restrict__ bz, const float* __restrict__ nz,
                float* __restrict__ z_out)
{
    int i = (blockIdx.x * 256 + threadIdx.x) << 2;   // 128 blocks
    float4 s = make_float4(0.f, 0.f, 0.f, 0.f);
#pragma unroll
    for (int c = 0; c < 8; c++) {
        float4 p = *reinterpret_cast<const float4*>(&g_pz[c][i]);
        s.x += p.x; s.y += p.y; s.z += p.z; s.w += p.w;
    }
    float4 bb = *reinterpret_cast<const float4*>(bz + (i & (DIM - 1)));
    float4 nn = *reinterpret_cast<const float4*>(nz + i);
    float4 r;
    r.x = s.x + bb.x + SIGMA * nn.x;
    r.y = s.y + bb.y + SIGMA * nn.y;
    r.z = s.z + bb.z + SIGMA * nn.z;
    r.w = s.w + bb.w + SIGMA * nn.w;
    *reinterpret_cast<float4*>(z_out + i) = r;
}

// ---------------- copy K -> K_out (with slot write) + logits ----------------
// (R1/R5/R12 form — verbatim: 82% DRAM measured; zero added work)
__global__ void __launch_bounds__(256)
copyK_kernel(const float* __restrict__ K, float* __restrict__ Kout,
             float* __restrict__ logits, const int* __restrict__ tptr)
{
    const int bp  = blockIdx.y;
    const int s0  = blockIdx.x * 32;
    const int tid = threadIdx.x;
    const int t   = *tptr;

    __shared__ float pds[32][256];   // per-s, per-thread partial dot

    float4 q4 = *reinterpret_cast<const float4*>(g_qp + bp * DIM + (tid << 2));
    const float* kprow = g_kp + bp * DIM;
    const float* Kb = K    + (size_t)bp * SEQ * DIM;
    float*       Ob = Kout + (size_t)bp * SEQ * DIM;

#pragma unroll 4
    for (int sl = 0; sl < 32; sl++) {
        int s = s0 + sl;
        const float* src = (s == t) ? kprow : (Kb + (size_t)s * DIM);
        float4 v = *reinterpret_cast<const float4*>(src + (tid << 2));
        *reinterpret_cast<float4*>(Ob + (size_t)s * DIM + (tid << 2)) = v;
        pds[sl][tid] = v.x * q4.x + v.y * q4.y + v.z * q4.z + v.w * q4.w;
    }
    __syncthreads();

    for (int i = tid; i < 512; i += 256) {
        int h  = i & 15;
        int sl = i >> 4;
        float sum = 0.f;
#pragma unroll
        for (int j = 0; j < 16; j++) sum += pds[sl][(h << 4) + j];
        logits[((size_t)(bp * NH + h)) * SEQ + s0 + sl] = sum * SCALE;
    }
}

// ---------------- softmax in place over attn region (rows of 1024) ----------
// one warp per row; 512 blocks x 128 threads (R12 form)
__global__ void __launch_bounds__(128)
softmax_kernel(float* __restrict__ attn)
{
    int row  = blockIdx.x * 4 + (threadIdx.x >> 5);   // 2048 rows
    int lane = threadIdx.x & 31;
    float* p = attn + (size_t)row * SEQ;

    float v[32];
    float m = -1e30f;
#pragma unroll
    for (int i = 0; i < 32; i++) { v[i] = p[lane + (i << 5)]; m = fmaxf(m, v[i]); }
#pragma unroll
    for (int o = 16; o > 0; o >>= 1) m = fmaxf(m, __shfl_xor_sync(0xffffffffu, m, o));
    float sum = 0.f;
#pragma unroll
    for (int i = 0; i < 32; i++) { v[i] = __expf(v[i] - m); sum += v[i]; }
#pragma unroll
    for (int o = 16; o > 0; o >>= 1) sum += __shfl_xor_sync(0xffffffffu, sum, o);
    float inv = 1.f / sum;
#pragma unroll
    for (int i = 0; i < 32; i++) p[lane + (i << 5)] = v[i] * inv;
}

// ---------------- copy V -> V_out (slot write) + attn-weighted partials -----
// (R1/R5/R12 form — verbatim; zero added work)
__global__ void __launch_bounds__(256)
copyV_kernel(const float* __restrict__ V, float* __restrict__ Vout,
             const float* __restrict__ attn, const int* __restrict__ tptr)
{
    const int bp  = blockIdx.y;
    const int s0  = blockIdx.x * 32;
    const int tid = threadIdx.x;
    const int t   = *tptr;

    __shared__ float as[NH][32];
    for (int i = tid; i < NH * 32; i += 256) {
        int h  = i >> 5;
        int sl = i & 31;
        as[h][sl] = attn[((size_t)(bp * NH + h)) * SEQ + s0 + sl];
    }
    __syncthreads();

    const float* vprow = g_vp + bp * DIM;
    const float* Vb = V    + (size_t)bp * SEQ * DIM;
    float*       Ob = Vout + (size_t)bp * SEQ * DIM;

    const int h = tid >> 4;   // head of cols 4t..4t+3
    float4 acc = make_float4(0.f, 0.f, 0.f, 0.f);

#pragma unroll 4
    for (int sl = 0; sl < 32; sl++) {
        int s = s0 + sl;
        const float* src = (s == t) ? vprow : (Vb + (size_t)s * DIM);
        float4 v = *reinterpret_cast<const float4*>(src + (tid << 2));
        *reinterpret_cast<float4*>(Ob + (size_t)s * DIM + (tid << 2)) = v;
        float a = as[h][sl];
        acc.x += a * v.x; acc.y += a * v.y; acc.z += a * v.z; acc.w += a * v.w;
    }
    *reinterpret_cast<float4*>(g_part + ((size_t)blockIdx.x * BP + bp) * DIM + (tid << 2)) = acc;
}

// ---------------- reduce the 32 s-chunk partials into g_zh (float4) ---------
__global__ void __launch_bounds__(256)
reduce_kernel()
{
    int i = (blockIdx.x * 256 + threadIdx.x) << 2;   // 128 blocks over BP*DIM
    float4 s = make_float4(0.f, 0.f, 0.f, 0.f);
#pragma unroll
    for (int c = 0; c < 32; c++) {
        float4 p = *reinterpret_cast<const float4*>(&g_part[(size_t)c * (BP * DIM) + i]);
        s.x += p.x; s.y += p.y; s.z += p.z; s.w += p.w;
    }
    *reinterpret_cast<float4*>(&g_zh[i]) = s;
}

// ---------------- launch ----------------------------------------------------
extern "C" void kernel_launch(void* const* d_in, const int* in_sizes, int n_in,
                              void* d_out, int out_size)
{
    const float* q   = (const float*)d_in[0];
    const float* k   = (const float*)d_in[1];
    const float* v   = (const float*)d_in[2];
    const float* Kin = (const float*)d_in[3];
    const float* Vin = (const float*)d_in[4];
    const float* Wq  = (const float*)d_in[5];
    const float* bq  = (const float*)d_in[6];
    const float* Wk  = (const float*)d_in[7];
    const float* bk  = (const float*)d_in[8];
    const float* Wv  = (const float*)d_in[9];
    const float* bv  = (const float*)d_in[10];
    const float* Wz  = (const float*)d_in[11];
    const float* bz  = (const float*)d_in[12];
    const float* nq  = (const float*)d_in[13];
    const float* nk  = (const float*)d_in[14];
    const float* nv  = (const float*)d_in[15];
    const float* nz  = (const float*)d_in[16];
    const int* tstep = (const int*)d_in[17];

    float* out   = (float*)d_out;
    float* z_out = out;                                       // 128*1024
    float* K_out = out + (size_t)BP * DIM;                    // 128*1024*1024
    float* V_out = K_out + (size_t)BP * SEQ * DIM;
    float* attn  = V_out + (size_t)BP * SEQ * DIM;            // 128*16*1024

    // 1. q/k/v projection partials (k-split x4, 4x4 micro-tile) + combine
    proj3_kernel<<<dim3(32, 3, 4), 256>>>(q, k, v, Wq, Wk, Wv);
    combine3_kernel<<<dim3(128, 3), 256>>>(bq, bk, bv, nq, nk, nv);
    // 2. K copy (slot write at t) fused with logits
    copyK_kernel<<<dim3(32, BP), 256>>>(Kin, K_out, attn, tstep);
    // 3. softmax in place
    softmax_kernel<<<512, 128>>>(attn);
    // 4. V copy (slot write at t) fused with attn-weighted partial sums
    copyV_kernel<<<dim3(32, BP), 256>>>(Vin, V_out, attn, tstep);
    // 5. reduce partials -> zh (float4)
    reduce_kernel<<<128, 256>>>();
    // 6. z projection partials (k-split x8) + combine
    projZ_kernel<<<dim3(32, 1, 8), 256>>>(Wz);
    combineZ_kernel<<<128, 256>>>(bz, nz, z_out);
}